// round 13
// baseline (speedup 1.0000x reference)
#include <cuda_runtime.h>
#include <mma.h>
#include <math.h>
#include <cstdint>
#include <cuda_fp16.h>

using namespace nvcuda;

#define BATCH 256
#define DIN   512
#define TSEQ  512
#define HID   1024
#define NG    4096
#define KTOT  1536
#define NCLS  1000

#define NBLK  128       // persistent blocks, one per SM, 32 gate-cols each
#define NB    32
#define NWARP 16        // 8 row-groups x 2 k-halves
#define NGRP  8
#define GROWS 32        // batch rows per group
#define WLDH  1544      // sW column stride in halves (3088 B, 16B multiple)
#define KC    32        // halves per chunk
#define NPOS  (KTOT / KC)   // 48 chunk positions (x-first order)
#define NPW   (NPOS / 2)    // 24 chunks per warp (its k-half, interleaved)
#define NSTG  2
#define ALDH  40            // A stage row stride in halves (80 B, 16B multiple)
#define AWSZ  (GROWS * ALDH)   // per-warp A stage: 1280 halves = 2560 B

// SMEM layout (bytes)
#define OFF_W    0
#define W_BYTES  (NB * WLDH * 2)                  // 98,816
#define OFF_A    W_BYTES
#define A_BYTES  (NWARP * NSTG * AWSZ * 2)        // 81,920
#define OFF_C    (OFF_A + A_BYTES)                // 180,736
#define C_BYTES  (NGRP * GROWS * 32 * 4)          // 32,768 (ld=32 floats: 128 B, legal)
#define OFF_BIAS (OFF_C + C_BYTES)                // 213,504
#define SMEM_BYTES (OFF_BIAS + 128)               // 213,632  (< 227 KB)

// ---------------- static device scratch ----------------
__device__ __half g_xh[(size_t)TSEQ * BATCH * DIN];  // x transposed [T][B][D], fp16
__device__ __half g_Wh[(size_t)KTOT * NG];           // [Wh; Wx] gate-interleaved, fp16
__device__ float  g_bias[NG];
__device__ __half g_h[2][(size_t)BATCH * HID];       // double-buffered hidden state (fp16)
__device__ float  g_c[(size_t)BATCH * HID];          // cell state (fp32)
__device__ unsigned g_arrive;
__device__ unsigned g_release;

__device__ __forceinline__ unsigned ld_acquire(const unsigned* p) {
    unsigned v;
    asm volatile("ld.acquire.gpu.global.u32 %0, [%1];" : "=r"(v) : "l"(p));
    return v;
}
__device__ __forceinline__ void st_release(unsigned* p, unsigned v) {
    asm volatile("st.release.gpu.global.u32 [%0], %1;" :: "l"(p), "r"(v));
}
__device__ __forceinline__ void cp16(uint32_t dst, const void* src) {
    asm volatile("cp.async.cg.shared.global [%0], [%1], 16;\n" :: "r"(dst), "l"(src));
}
__device__ __forceinline__ void cp_commit() {
    asm volatile("cp.async.commit_group;\n");
}
template <int N>
__device__ __forceinline__ void cp_wait() {
    asm volatile("cp.async.wait_group %0;\n" :: "n"(N));
}

// ---------------- init ----------------
__global__ void init_kernel() {
    size_t i = blockIdx.x * (size_t)blockDim.x + threadIdx.x;
    if (i < (size_t)BATCH * HID) {
        g_h[0][i] = __float2half(0.0f);
        g_c[i]    = 0.0f;
    }
    if (i == 0) { g_arrive = 0u; g_release = 0u; }
}

// ---------------- pack weights: g_Wh[k][u*4+gate], gates (g,f,i,o), fp16 ----------------
__global__ void pack_kernel(const float* __restrict__ Wfx, const float* __restrict__ Wfh,
                            const float* __restrict__ Wgx, const float* __restrict__ Wgh,
                            const float* __restrict__ Wix, const float* __restrict__ Wih,
                            const float* __restrict__ Wox, const float* __restrict__ Woh,
                            const float* __restrict__ bf,  const float* __restrict__ bg,
                            const float* __restrict__ bi,  const float* __restrict__ bo) {
    size_t idx = blockIdx.x * (size_t)blockDim.x + threadIdx.x;
    size_t total = (size_t)KTOT * NG;
    if (idx >= total) return;
    int e = (int)(idx % NG);
    int k = (int)(idx / NG);
    int u = e >> 2;
    int gate = e & 3;
    float v;
    if (k < HID) {
        const float* W = (gate == 0) ? Wgh : (gate == 1) ? Wfh : (gate == 2) ? Wih : Woh;
        v = W[(size_t)k * HID + u];
    } else {
        int d = k - HID;
        const float* W = (gate == 0) ? Wgx : (gate == 1) ? Wfx : (gate == 2) ? Wix : Wox;
        v = W[(size_t)d * HID + u];
    }
    g_Wh[idx] = __float2half(v);
    if (idx < NG) {
        const float* b = (gate == 0) ? bg : (gate == 1) ? bf : (gate == 2) ? bi : bo;
        g_bias[e] = b[u];
    }
}

// ---------------- transpose x [B,D,T] -> xh [T][B*D], fp16 ----------------
__global__ void transpose_kernel(const float* __restrict__ x) {
    __shared__ float tile[32][33];
    int t0 = blockIdx.x * 32;
    int r0 = blockIdx.y * 32;
    int tx = threadIdx.x;
    int ty = threadIdx.y;     // blockDim = (32, 8)
#pragma unroll
    for (int i = 0; i < 32; i += 8)
        tile[ty + i][tx] = x[(size_t)(r0 + ty + i) * TSEQ + (t0 + tx)];
    __syncthreads();
#pragma unroll
    for (int i = 0; i < 32; i += 8)
        g_xh[(size_t)(t0 + ty + i) * (BATCH * DIN) + (r0 + tx)] = __float2half(tile[tx][ty + i]);
}

// ================= persistent LSTM kernel, fp16 MMA, k-split =================
// 128 blocks x 512 threads. Block owns gate-cols n0..n0+31. 16 warps = 8 row-
// groups x 2 k-halves; each warp computes an m32n32 partial over its k-half
// (interleaved chunks, x-part first). Partials summed once per step via SMEM +
// fragment add; e=1 warp runs the group's fused epilogue while e=0 prefetches
// next step's x chunks ahead of the grid softbarrier.
__global__ void __launch_bounds__(512) lstm_persistent_kernel() {
    extern __shared__ char smem[];
    __half* sW    = reinterpret_cast<__half*>(smem + OFF_W);
    float*  sBias = reinterpret_cast<float*>(smem + OFF_BIAS);

    const int tid  = threadIdx.x;
    const int warp = tid >> 5;
    const int lane = tid & 31;
    const int grp  = warp >> 1;               // row group 0..7
    const int eh   = warp & 1;                // k-half 0/1
    const int n0   = blockIdx.x * NB;
    const int m0   = grp * GROWS;             // this group's batch rows
    __half* sA = reinterpret_cast<__half*>(smem + OFF_A) + warp * (NSTG * AWSZ);
    float*  sC = reinterpret_cast<float*>(smem + OFF_C) + grp * (GROWS * 32);

    uint32_t sA_base;
    {
        void* p = (void*)sA;
        asm("{ .reg .u64 tt; cvta.to.shared.u64 tt, %1; cvt.u32.u64 %0, tt; }"
            : "=r"(sA_base) : "l"(p));
    }

    // ---- one-time: W slice into SMEM: sW[n][k] = g_Wh[k][n0+n] ----
    for (int idx = tid; idx < KTOT * NB; idx += 512) {
        int k = idx >> 5;
        int n = idx & 31;
        sW[n * WLDH + k] = g_Wh[(size_t)k * NG + n0 + n];
    }
    if (tid < NB) sBias[tid] = g_bias[n0 + tid];

    const int eu   = lane & 7;                // epilogue unit 0..7
    const int ersb = lane >> 3;               // epilogue row sub 0..3
    const int u0   = n0 >> 2;
    __syncthreads();
    const float bias_g = sBias[eu * 4 + 0];
    const float bias_f = sBias[eu * 4 + 1];
    const float bias_i = sBias[eu * 4 + 2];
    const float bias_o = sBias[eu * 4 + 3];

    // chunk position -> k offset: positions 0..15 are the x part (k 1024..1535),
    // positions 16..47 the h part (k 0..1023). Warp eh takes positions 2p+eh.
    auto kc_of = [&](int p) {
        int pos = 2 * p + eh;
        return (pos < 16) ? (1024 + pos * KC) : ((pos - 16) * KC);
    };

    // stage this group's 32 rows x KC halves from [h | x_t]; 4 cp16 per lane
    auto stage = [&](int s, int kc, const __half* hin, const __half* xTt) {
        const __half* srcbase;
        int rstride;
        if (kc < HID) { srcbase = hin + (size_t)m0 * HID + kc;         rstride = HID; }
        else          { srcbase = xTt + (size_t)m0 * DIN + (kc - HID); rstride = DIN; }
        uint32_t dst0 = sA_base + (uint32_t)(s * AWSZ) * 2u;
#pragma unroll
        for (int j = 0; j < 4; ++j) {
            int idx = j * 32 + lane;      // 128 x 16B
            int row = idx >> 2;
            int q   = idx & 3;
            cp16(dst0 + (uint32_t)(row * ALDH + q * 8) * 2u,
                 srcbase + (size_t)row * rstride + q * 8);
        }
        cp_commit();
    };

    // initial prefetch for t=0 (positions 0,1 per warp: x chunks, h-independent)
    {
        const __half* xT0 = g_xh;
        stage(0, kc_of(0), nullptr, xT0);
        stage(1, kc_of(1), nullptr, xT0);
    }

    for (int t = 0; t < TSEQ; ++t) {
        const __half* __restrict__ hin  = g_h[t & 1];
        __half*       __restrict__ hout = g_h[(t + 1) & 1];
        const __half* __restrict__ xTt  = g_xh + (size_t)t * (BATCH * DIN);

        wmma::fragment<wmma::accumulator, 16, 16, 16, float> acc[2][2];
#pragma unroll
        for (int am = 0; am < 2; ++am)
#pragma unroll
            for (int bn = 0; bn < 2; ++bn)
                wmma::fill_fragment(acc[am][bn], 0.0f);

        for (int p = 0; p < NPW; ++p) {
            cp_wait<1>();
            __syncwarp();
            const __half* cA = sA + (p & 1) * AWSZ;
            const int kc = kc_of(p);

#pragma unroll
            for (int kk = 0; kk < KC; kk += 16) {
                wmma::fragment<wmma::matrix_a, 16, 16, 16, __half, wmma::row_major> af[2];
                wmma::fragment<wmma::matrix_b, 16, 16, 16, __half, wmma::col_major> bfr[2];
#pragma unroll
                for (int am = 0; am < 2; ++am)
                    wmma::load_matrix_sync(af[am], cA + (am * 16) * ALDH + kk, ALDH);
#pragma unroll
                for (int bn = 0; bn < 2; ++bn)
                    wmma::load_matrix_sync(bfr[bn], sW + (bn * 16) * WLDH + kc + kk, WLDH);
#pragma unroll
                for (int am = 0; am < 2; ++am)
#pragma unroll
                    for (int bn = 0; bn < 2; ++bn)
                        wmma::mma_sync(acc[am][bn], af[am], bfr[bn], acc[am][bn]);
            }

            if (p + 2 < NPW) stage(p & 1, kc_of(p + 2), hin, xTt);
            else             cp_commit();   // keep group count consistent
        }
        cp_wait<0>();
        __syncwarp();

        // ---- k-half reduce + fused epilogue ----
        if (eh == 0) {
#pragma unroll
            for (int am = 0; am < 2; ++am)
#pragma unroll
                for (int bn = 0; bn < 2; ++bn)
                    wmma::store_matrix_sync(sC + (am * 16) * 32 + bn * 16,
                                            acc[am][bn], 32, wmma::mem_row_major);
        }
        __syncthreads();
        if (eh == 1) {
#pragma unroll
            for (int am = 0; am < 2; ++am)
#pragma unroll
                for (int bn = 0; bn < 2; ++bn) {
                    wmma::fragment<wmma::accumulator, 16, 16, 16, float> pf;
                    wmma::load_matrix_sync(pf, sC + (am * 16) * 32 + bn * 16,
                                           32, wmma::mem_row_major);
#pragma unroll
                    for (int i = 0; i < pf.num_elements; ++i)
                        acc[am][bn].x[i] += pf.x[i];
                    wmma::store_matrix_sync(sC + (am * 16) * 32 + bn * 16,
                                            acc[am][bn], 32, wmma::mem_row_major);
                }
            __syncwarp();

#pragma unroll
            for (int j = 0; j < 8; ++j) {
                int r = j * 4 + ersb;             // 0..31
                float gg = tanhf(sC[r * 32 + eu * 4 + 0] + bias_g);
                float ff = tanhf(sC[r * 32 + eu * 4 + 1] + bias_f);
                float ii = tanhf(sC[r * 32 + eu * 4 + 2] + bias_i);
                float oo = tanhf(sC[r * 32 + eu * 4 + 3] + bias_o);
                size_t cidx = (size_t)(m0 + r) * HID + (u0 + eu);
                float c = gg * ii + g_c[cidx] * ff;
                g_c[cidx]  = c;
                hout[cidx] = __float2half(tanhf(c) * oo);
            }
        }

        // ---- prefetch next step's first two x chunks (h-independent) ----
        if (t + 1 < TSEQ) {
            const __half* xTn = g_xh + (size_t)(t + 1) * (BATCH * DIN);
            stage(0, kc_of(0), nullptr, xTn);
            stage(1, kc_of(1), nullptr, xTn);
        }

        // ---- grid softbarrier ----
        __threadfence();
        __syncthreads();
        if (tid == 0) {
            unsigned cnt    = atomicAdd(&g_arrive, 1u) + 1u;
            unsigned target = (unsigned)NBLK * (unsigned)(t + 1);
            if (cnt == target) {
                __threadfence();
                st_release(&g_release, (unsigned)(t + 1));
            } else {
                while (ld_acquire(&g_release) < (unsigned)(t + 1)) { }
            }
        }
        __syncthreads();
    }
}

// ---------------- head: softmax(h @ W_ph + b_p) ----------------
__global__ void __launch_bounds__(256) head_kernel(const float* __restrict__ Wph,
                                                   const float* __restrict__ bp,
                                                   float* __restrict__ out) {
    __shared__ float hs[HID];
    __shared__ float lg[NCLS];
    __shared__ float red[256];
    int b   = blockIdx.x;
    int tid = threadIdx.x;
    const __half* h = g_h[0];   // after 512 steps, final h lives in buffer 0

    for (int i = tid; i < HID; i += 256)
        hs[i] = __half2float(h[(size_t)b * HID + i]);
    __syncthreads();

    for (int c = tid; c < NCLS; c += 256) {
        float acc = bp[c];
#pragma unroll 8
        for (int k = 0; k < HID; ++k)
            acc += hs[k] * Wph[(size_t)k * NCLS + c];
        lg[c] = acc;
    }
    __syncthreads();

    float m = -1e30f;
    for (int c = tid; c < NCLS; c += 256) m = fmaxf(m, lg[c]);
    red[tid] = m;
    __syncthreads();
    for (int s = 128; s > 0; s >>= 1) {
        if (tid < s) red[tid] = fmaxf(red[tid], red[tid + s]);
        __syncthreads();
    }
    m = red[0];
    __syncthreads();

    float sum = 0.0f;
    for (int c = tid; c < NCLS; c += 256) {
        float ex = expf(lg[c] - m);
        lg[c] = ex;
        sum += ex;
    }
    red[tid] = sum;
    __syncthreads();
    for (int s = 128; s > 0; s >>= 1) {
        if (tid < s) red[tid] += red[tid + s];
        __syncthreads();
    }
    float inv = 1.0f / red[0];
    for (int c = tid; c < NCLS; c += 256)
        out[(size_t)b * NCLS + c] = lg[c] * inv;
}

// ---------------- launch ----------------
extern "C" void kernel_launch(void* const* d_in, const int* in_sizes, int n_in,
                              void* d_out, int out_size) {
    (void)in_sizes; (void)n_in; (void)out_size;
    const float* x   = (const float*)d_in[0];
    const float* Wfx = (const float*)d_in[1];
    const float* Wfh = (const float*)d_in[2];
    const float* Wgx = (const float*)d_in[3];
    const float* Wgh = (const float*)d_in[4];
    const float* Wix = (const float*)d_in[5];
    const float* Wih = (const float*)d_in[6];
    const float* Wox = (const float*)d_in[7];
    const float* Woh = (const float*)d_in[8];
    const float* Wph = (const float*)d_in[9];
    const float* bf  = (const float*)d_in[10];
    const float* bg  = (const float*)d_in[11];
    const float* bi  = (const float*)d_in[12];
    const float* bo  = (const float*)d_in[13];
    const float* bp  = (const float*)d_in[14];
    float* out = (float*)d_out;

    cudaFuncSetAttribute(lstm_persistent_kernel,
                         cudaFuncAttributeMaxDynamicSharedMemorySize, SMEM_BYTES);

    init_kernel<<<(BATCH * HID + 255) / 256, 256>>>();

    size_t packN = (size_t)KTOT * NG;
    pack_kernel<<<(unsigned)((packN + 255) / 256), 256>>>(Wfx, Wfh, Wgx, Wgh,
                                                          Wix, Wih, Wox, Woh,
                                                          bf, bg, bi, bo);

    transpose_kernel<<<dim3(TSEQ / 32, (BATCH * DIN) / 32), dim3(32, 8)>>>(x);

    lstm_persistent_kernel<<<NBLK, 512, SMEM_BYTES>>>();

    head_kernel<<<BATCH, 256>>>(Wph, bp, out);
}